// round 1
// baseline (speedup 1.0000x reference)
#include <cuda_runtime.h>
#include <cuda_bf16.h>
#include <cstdint>

// ComboSumModule: 6 tensors (N=2048, M_i, K_i) float32, sum over axis 1.
// Outputs (2048, K_i) concatenated in order into d_out.
//
// Shapes (fixed by the problem instance):
//   x0: (2048,128,64)  x1: (2048,32,32)  x2: (2048,64,64)
//   x3: (2048,16,48)   x4: (2048,200,32) x5: (2048,8,8)
//
// Strategy: fully fused, float4-vectorized, one work item per output float4.
// Work item i within a segment: n = i / Kv, k = i % Kv (Kv = K/4).
// Inner loop over M with stride Kv float4s; dual accumulators + unroll for MLP.

template<int M, int Kv>
__device__ __forceinline__ void seg_reduce(const float* __restrict__ in,
                                           float* __restrict__ out, int i) {
    const int n = i / Kv;
    const int k = i - n * Kv;
    const float4* __restrict__ p =
        reinterpret_cast<const float4*>(in) + (size_t)n * (size_t)(M * Kv) + k;

    float4 a = make_float4(0.f, 0.f, 0.f, 0.f);
    float4 b = make_float4(0.f, 0.f, 0.f, 0.f);
    // All M are even (128,32,64,16,200,8): process 2 per iter, 2 accumulators.
    #pragma unroll 8
    for (int m = 0; m < M; m += 2) {
        float4 v = __ldg(p + (size_t)m * Kv);
        float4 w = __ldg(p + (size_t)(m + 1) * Kv);
        a.x += v.x; a.y += v.y; a.z += v.z; a.w += v.w;
        b.x += w.x; b.y += w.y; b.z += w.z; b.w += w.w;
    }
    float4 s;
    s.x = a.x + b.x; s.y = a.y + b.y; s.z = a.z + b.z; s.w = a.w + b.w;
    reinterpret_cast<float4*>(out)[i] = s;
}

// float4 work-item counts per segment (N * K/4):
//   c0=32768 c1=16384 c2=32768 c3=24576 c4=16384 c5=4096  -> total 126976
// cumulative:   32768   49152   81920   106496  122880  126976
// output float offsets: 0, 131072, 196608, 327680, 425984, 491520

static constexpr int TOTAL_VEC = 126976;

__global__ __launch_bounds__(256)
void combo_sum_kernel(const float* __restrict__ x0, const float* __restrict__ x1,
                      const float* __restrict__ x2, const float* __restrict__ x3,
                      const float* __restrict__ x4, const float* __restrict__ x5,
                      float* __restrict__ out) {
    int i = blockIdx.x * 256 + threadIdx.x;
    if (i >= TOTAL_VEC) return;

    if (i < 32768) {
        seg_reduce<128, 16>(x0, out + 0, i);
    } else if (i < 49152) {
        seg_reduce<32, 8>(x1, out + 131072, i - 32768);
    } else if (i < 81920) {
        seg_reduce<64, 16>(x2, out + 196608, i - 49152);
    } else if (i < 106496) {
        seg_reduce<16, 12>(x3, out + 327680, i - 81920);
    } else if (i < 122880) {
        seg_reduce<200, 8>(x4, out + 425984, i - 106496);
    } else {
        seg_reduce<8, 2>(x5, out + 491520, i - 122880);
    }
}

extern "C" void kernel_launch(void* const* d_in, const int* in_sizes, int n_in,
                              void* d_out, int out_size) {
    const float* x0 = (const float*)d_in[0];
    const float* x1 = (const float*)d_in[1];
    const float* x2 = (const float*)d_in[2];
    const float* x3 = (const float*)d_in[3];
    const float* x4 = (const float*)d_in[4];
    const float* x5 = (const float*)d_in[5];
    float* out = (float*)d_out;

    const int threads = 256;
    const int blocks = (TOTAL_VEC + threads - 1) / threads;  // 496
    combo_sum_kernel<<<blocks, threads>>>(x0, x1, x2, x3, x4, x5, out);
}

// round 2
// speedup vs baseline: 1.3378x; 1.3378x over previous
#include <cuda_runtime.h>
#include <cuda_bf16.h>
#include <cstdint>

// ComboSumModule: 6 tensors (N=2048, M_i, K_i) fp32, sum over axis 1.
//   x0:(2048,128,64) x1:(2048,32,32) x2:(2048,64,64)
//   x3:(2048,16,48)  x4:(2048,200,32) x5:(2048,8,8)
// Output float offsets: 0, 131072, 196608, 327680, 425984, 491520 (total 507904).
//
// R2 strategy: balance the load. Long M reductions are split into ~32-row
// chunks; each work item streams ~512B and either plain-stores (S==1) or
// combines partials with one red.global.add.v4.f32. Split regions are
// zero-initialized by a small kernel launched first (both graph-capturable).

__device__ __forceinline__ void f4_acc(float4& a, const float4 v) {
    a.x += v.x; a.y += v.y; a.z += v.z; a.w += v.w;
}

__device__ __forceinline__ void red_add_v4(float4* q, const float4 v) {
    asm volatile("red.global.add.v4.f32 [%0], {%1, %2, %3, %4};"
                 :: "l"(__cvta_generic_to_global(q)),
                    "f"(v.x), "f"(v.y), "f"(v.z), "f"(v.w)
                 : "memory");
}

// M = rows, Kv = K/4, S = number of M-splits, C = rows per split (S*C >= M,
// last split may be shorter only if S*C==M; here all chosen so S*C==M).
template<int M, int Kv, int S, int C>
__device__ __forceinline__ void seg_reduce(const float* __restrict__ in,
                                           float* __restrict__ out, int j) {
    const int k = j % Kv;
    const int t = j / Kv;
    const int s = (S == 1) ? 0 : (t % S);
    const int n = (S == 1) ? t : (t / S);

    const float4* __restrict__ p = reinterpret_cast<const float4*>(in)
                                 + (size_t)n * (size_t)(M * Kv)
                                 + (size_t)(s * C) * Kv + k;

    float4 acc[4];
    acc[0] = acc[1] = acc[2] = acc[3] = make_float4(0.f, 0.f, 0.f, 0.f);
    #pragma unroll
    for (int m = 0; m < C; ++m) {
        f4_acc(acc[m & 3], __ldg(p + (size_t)m * Kv));
    }
    float4 sum;
    sum.x = (acc[0].x + acc[1].x) + (acc[2].x + acc[3].x);
    sum.y = (acc[0].y + acc[1].y) + (acc[2].y + acc[3].y);
    sum.z = (acc[0].z + acc[1].z) + (acc[2].z + acc[3].z);
    sum.w = (acc[0].w + acc[1].w) + (acc[2].w + acc[3].w);

    float4* q = reinterpret_cast<float4*>(out) + (size_t)n * Kv + k;
    if (S == 1) {
        *q = sum;
    } else {
        red_add_v4(q, sum);
    }
}

// Item counts per segment = N * Kv * S:
//  seg0: 2048*16*4 = 131072   cum 131072
//  seg1: 2048*8*1  = 16384    cum 147456
//  seg2: 2048*16*2 = 65536    cum 212992
//  seg3: 2048*12*1 = 24576    cum 237568
//  seg4: 2048*8*8  = 131072   cum 368640
//  seg5: 2048*2*1  = 4096     cum 372736
static constexpr int TOTAL_ITEMS = 372736;

__global__ __launch_bounds__(256, 4)
void combo_sum_kernel(const float* __restrict__ x0, const float* __restrict__ x1,
                      const float* __restrict__ x2, const float* __restrict__ x3,
                      const float* __restrict__ x4, const float* __restrict__ x5,
                      float* __restrict__ out) {
    int j = blockIdx.x * 256 + threadIdx.x;
    if (j >= TOTAL_ITEMS) return;

    if (j < 131072) {
        seg_reduce<128, 16, 4, 32>(x0, out + 0,       j);
    } else if (j < 147456) {
        seg_reduce<32,  8,  1, 32>(x1, out + 131072,  j - 131072);
    } else if (j < 212992) {
        seg_reduce<64,  16, 2, 32>(x2, out + 196608,  j - 147456);
    } else if (j < 237568) {
        seg_reduce<16,  12, 1, 16>(x3, out + 327680,  j - 212992);
    } else if (j < 368640) {
        seg_reduce<200, 8,  8, 25>(x4, out + 425984,  j - 237568);
    } else {
        seg_reduce<8,   2,  1, 8 >(x5, out + 491520,  j - 368640);
    }
}

// Zero only the atomically-accumulated regions:
//  seg0 floats [0, 131072)        -> f4 [0, 32768)
//  seg2 floats [196608, 327680)   -> f4 [49152, 81920)
//  seg4 floats [425984, 491520)   -> f4 [106496, 122880)
static constexpr int ZERO_ITEMS = 32768 + 32768 + 16384;  // 81920 float4

__global__ __launch_bounds__(256)
void zero_split_regions(float* __restrict__ out) {
    int i = blockIdx.x * 256 + threadIdx.x;
    if (i >= ZERO_ITEMS) return;
    float4* o4 = reinterpret_cast<float4*>(out);
    int idx;
    if (i < 32768)       idx = i;                       // seg0
    else if (i < 65536)  idx = 49152  + (i - 32768);    // seg2
    else                 idx = 106496 + (i - 65536);    // seg4
    o4[idx] = make_float4(0.f, 0.f, 0.f, 0.f);
}

extern "C" void kernel_launch(void* const* d_in, const int* in_sizes, int n_in,
                              void* d_out, int out_size) {
    const float* x0 = (const float*)d_in[0];
    const float* x1 = (const float*)d_in[1];
    const float* x2 = (const float*)d_in[2];
    const float* x3 = (const float*)d_in[3];
    const float* x4 = (const float*)d_in[4];
    const float* x5 = (const float*)d_in[5];
    float* out = (float*)d_out;

    zero_split_regions<<<(ZERO_ITEMS + 255) / 256, 256>>>(out);
    combo_sum_kernel<<<(TOTAL_ITEMS + 255) / 256, 256>>>(x0, x1, x2, x3, x4, x5, out);
}

// round 4
// speedup vs baseline: 1.4248x; 1.0650x over previous
#include <cuda_runtime.h>
#include <cuda_bf16.h>
#include <cstdint>

// ComboSumModule: 6 tensors (N=2048, M_i, K_i) fp32, sum over axis 1.
//   x0:(2048,128,64) x1:(2048,32,32) x2:(2048,64,64)
//   x3:(2048,16,48)  x4:(2048,200,32) x5:(2048,8,8)
// Output float offsets: 0, 131072, 196608, 327680, 425984, 491520 (total 507904).
//
// R3: balanced M-splits combined with warp butterfly shuffles -> no atomics,
// no zero-init kernel, single launch. Lane layout: lane = s*KW + k_local,
// KW = 32/G lanes of consecutive k (coalesced), G = #splits of M.

__device__ __forceinline__ void f4_acc(float4& a, const float4 v) {
    a.x += v.x; a.y += v.y; a.z += v.z; a.w += v.w;
}

// M rows, Kv = K/4 float4 per row, G = M-splits (power of 2, combined in-warp),
// C = M/G rows per split (G*C == M).
template<int M, int Kv, int G, int C>
__device__ __forceinline__ void seg_reduce(const float* __restrict__ in,
                                           float* __restrict__ out, int j) {
    const float4* __restrict__ in4 = reinterpret_cast<const float4*>(in);
    float4* __restrict__ out4 = reinterpret_cast<float4*>(out);

    float4 acc[4];
    acc[0] = acc[1] = acc[2] = acc[3] = make_float4(0.f, 0.f, 0.f, 0.f);

    if constexpr (G == 1) {
        const int k = j % Kv;
        const int n = j / Kv;
        const float4* __restrict__ p = in4 + (size_t)n * (size_t)(M * Kv) + k;
        #pragma unroll
        for (int m = 0; m < C; ++m)
            f4_acc(acc[m & 3], __ldg(p + (size_t)m * Kv));
        float4 s4;
        s4.x = (acc[0].x + acc[1].x) + (acc[2].x + acc[3].x);
        s4.y = (acc[0].y + acc[1].y) + (acc[2].y + acc[3].y);
        s4.z = (acc[0].z + acc[1].z) + (acc[2].z + acc[3].z);
        s4.w = (acc[0].w + acc[1].w) + (acc[2].w + acc[3].w);
        out4[(size_t)n * Kv + k] = s4;
    } else {
        constexpr int KW = 32 / G;       // k-lanes per split group
        constexpr int H  = Kv / KW;      // k-chunks per row handled by separate warps
        const int lane    = j & 31;
        const int k_local = lane & (KW - 1);
        const int s       = lane / KW;   // split index within warp
        const int rest    = j >> 5;
        const int h       = (H == 1) ? 0 : (rest % H);
        const int n       = (H == 1) ? rest : (rest / H);
        const int k       = h * KW + k_local;

        const float4* __restrict__ p = in4 + (size_t)n * (size_t)(M * Kv)
                                           + (size_t)(s * C) * Kv + k;
        #pragma unroll
        for (int m = 0; m < C; ++m)
            f4_acc(acc[m & 3], __ldg(p + (size_t)m * Kv));

        float4 s4;
        s4.x = (acc[0].x + acc[1].x) + (acc[2].x + acc[3].x);
        s4.y = (acc[0].y + acc[1].y) + (acc[2].y + acc[3].y);
        s4.z = (acc[0].z + acc[1].z) + (acc[2].z + acc[3].z);
        s4.w = (acc[0].w + acc[1].w) + (acc[2].w + acc[3].w);

        // Butterfly-combine the G splits (lanes differing in the s bits).
        #pragma unroll
        for (int d = KW; d < 32; d <<= 1) {
            s4.x += __shfl_xor_sync(0xFFFFFFFFu, s4.x, d);
            s4.y += __shfl_xor_sync(0xFFFFFFFFu, s4.y, d);
            s4.z += __shfl_xor_sync(0xFFFFFFFFu, s4.z, d);
            s4.w += __shfl_xor_sync(0xFFFFFFFFu, s4.w, d);
        }
        if (s == 0)
            out4[(size_t)n * Kv + k] = s4;
    }
}

// Thread counts per segment = N * Kv * G (all multiples of 32):
//  seg0: 2048*16*4 = 131072   cum 131072
//  seg1: 2048*8*1  = 16384    cum 147456
//  seg2: 2048*16*2 = 65536    cum 212992
//  seg3: 2048*12*1 = 24576    cum 237568
//  seg4: 2048*8*8  = 131072   cum 368640
//  seg5: 2048*2*1  = 4096     cum 372736
static constexpr int TOTAL_ITEMS = 372736;   // = 1456 * 256 exactly

__global__ __launch_bounds__(256, 4)
void combo_sum_kernel(const float* __restrict__ x0, const float* __restrict__ x1,
                      const float* __restrict__ x2, const float* __restrict__ x3,
                      const float* __restrict__ x4, const float* __restrict__ x5,
                      float* __restrict__ out) {
    const int j = blockIdx.x * 256 + threadIdx.x;

    if (j < 131072) {
        seg_reduce<128, 16, 4, 32>(x0, out + 0,       j);
    } else if (j < 147456) {
        seg_reduce<32,  8,  1, 32>(x1, out + 131072,  j - 131072);
    } else if (j < 212992) {
        seg_reduce<64,  16, 2, 32>(x2, out + 196608,  j - 147456);
    } else if (j < 237568) {
        seg_reduce<16,  12, 1, 16>(x3, out + 327680,  j - 212992);
    } else if (j < 368640) {
        seg_reduce<200, 8,  8, 25>(x4, out + 425984,  j - 237568);
    } else {
        seg_reduce<8,   2,  1, 8 >(x5, out + 491520,  j - 368640);
    }
}

extern "C" void kernel_launch(void* const* d_in, const int* in_sizes, int n_in,
                              void* d_out, int out_size) {
    const float* x0 = (const float*)d_in[0];
    const float* x1 = (const float*)d_in[1];
    const float* x2 = (const float*)d_in[2];
    const float* x3 = (const float*)d_in[3];
    const float* x4 = (const float*)d_in[4];
    const float* x5 = (const float*)d_in[5];
    float* out = (float*)d_out;

    combo_sum_kernel<<<TOTAL_ITEMS / 256, 256>>>(x0, x1, x2, x3, x4, x5, out);
}

// round 5
// speedup vs baseline: 1.4574x; 1.0229x over previous
#include <cuda_runtime.h>
#include <cuda_bf16.h>
#include <cstdint>

// ComboSumModule: 6 tensors (N=2048, M_i, K_i) fp32, sum over axis 1.
//   x0:(2048,128,64) x1:(2048,32,32) x2:(2048,64,64)
//   x3:(2048,16,48)  x4:(2048,200,32) x5:(2048,8,8)
// Output float offsets: 0, 131072, 196608, 327680, 425984, 491520.
//
// R5: same balanced M-split + warp-butterfly design as R3, but trade
// per-thread MLP for occupancy: __launch_bounds__(256,6) (<=42 regs),
// 2 accumulators. 48 warps/SM theoretical vs 32 before.

__device__ __forceinline__ void f4_acc(float4& a, const float4 v) {
    a.x += v.x; a.y += v.y; a.z += v.z; a.w += v.w;
}

// M rows, Kv = K/4 float4 per row, G = M-splits (power of 2, in-warp combine),
// C = rows per split (G*C == M, except seg4: 8*25=200).
template<int M, int Kv, int G, int C>
__device__ __forceinline__ void seg_reduce(const float* __restrict__ in,
                                           float* __restrict__ out, int j) {
    const float4* __restrict__ in4 = reinterpret_cast<const float4*>(in);
    float4* __restrict__ out4 = reinterpret_cast<float4*>(out);

    float4 a0 = make_float4(0.f, 0.f, 0.f, 0.f);
    float4 a1 = make_float4(0.f, 0.f, 0.f, 0.f);

    if constexpr (G == 1) {
        const int k = j % Kv;
        const int n = j / Kv;
        const float4* __restrict__ p = in4 + (size_t)n * (size_t)(M * Kv) + k;
        #pragma unroll
        for (int m = 0; m < C; ++m) {
            float4 v = __ldg(p + (size_t)m * Kv);
            if (m & 1) f4_acc(a1, v); else f4_acc(a0, v);
        }
        float4 s4;
        s4.x = a0.x + a1.x; s4.y = a0.y + a1.y;
        s4.z = a0.z + a1.z; s4.w = a0.w + a1.w;
        out4[(size_t)n * Kv + k] = s4;
    } else {
        constexpr int KW = 32 / G;       // k-lanes per split group
        constexpr int H  = Kv / KW;      // k-chunks per row across warps
        const int lane    = j & 31;
        const int k_local = lane & (KW - 1);
        const int s       = lane / KW;   // split index within warp
        const int rest    = j >> 5;
        const int h       = (H == 1) ? 0 : (rest % H);
        const int n       = (H == 1) ? rest : (rest / H);
        const int k       = h * KW + k_local;

        const float4* __restrict__ p = in4 + (size_t)n * (size_t)(M * Kv)
                                           + (size_t)(s * C) * Kv + k;
        #pragma unroll
        for (int m = 0; m < C; ++m) {
            float4 v = __ldg(p + (size_t)m * Kv);
            if (m & 1) f4_acc(a1, v); else f4_acc(a0, v);
        }

        float4 s4;
        s4.x = a0.x + a1.x; s4.y = a0.y + a1.y;
        s4.z = a0.z + a1.z; s4.w = a0.w + a1.w;

        // Butterfly-combine the G splits (lanes differing in the s bits).
        #pragma unroll
        for (int d = KW; d < 32; d <<= 1) {
            s4.x += __shfl_xor_sync(0xFFFFFFFFu, s4.x, d);
            s4.y += __shfl_xor_sync(0xFFFFFFFFu, s4.y, d);
            s4.z += __shfl_xor_sync(0xFFFFFFFFu, s4.z, d);
            s4.w += __shfl_xor_sync(0xFFFFFFFFu, s4.w, d);
        }
        if (s == 0)
            out4[(size_t)n * Kv + k] = s4;
    }
}

// Thread counts per segment = N * Kv * G (all multiples of 256):
//  seg0: 131072  cum 131072
//  seg1: 16384   cum 147456
//  seg2: 65536   cum 212992
//  seg3: 24576   cum 237568
//  seg4: 131072  cum 368640
//  seg5: 4096    cum 372736
static constexpr int TOTAL_ITEMS = 372736;   // = 1456 * 256 exactly

__global__ __launch_bounds__(256, 6)
void combo_sum_kernel(const float* __restrict__ x0, const float* __restrict__ x1,
                      const float* __restrict__ x2, const float* __restrict__ x3,
                      const float* __restrict__ x4, const float* __restrict__ x5,
                      float* __restrict__ out) {
    const int j = blockIdx.x * 256 + threadIdx.x;

    if (j < 131072) {
        seg_reduce<128, 16, 4, 32>(x0, out + 0,       j);
    } else if (j < 147456) {
        seg_reduce<32,  8,  1, 32>(x1, out + 131072,  j - 131072);
    } else if (j < 212992) {
        seg_reduce<64,  16, 2, 32>(x2, out + 196608,  j - 147456);
    } else if (j < 237568) {
        seg_reduce<16,  12, 1, 16>(x3, out + 327680,  j - 212992);
    } else if (j < 368640) {
        seg_reduce<200, 8,  8, 25>(x4, out + 425984,  j - 237568);
    } else {
        seg_reduce<8,   2,  1, 8 >(x5, out + 491520,  j - 368640);
    }
}

extern "C" void kernel_launch(void* const* d_in, const int* in_sizes, int n_in,
                              void* d_out, int out_size) {
    const float* x0 = (const float*)d_in[0];
    const float* x1 = (const float*)d_in[1];
    const float* x2 = (const float*)d_in[2];
    const float* x3 = (const float*)d_in[3];
    const float* x4 = (const float*)d_in[4];
    const float* x5 = (const float*)d_in[5];
    float* out = (float*)d_out;

    combo_sum_kernel<<<TOTAL_ITEMS / 256, 256>>>(x0, x1, x2, x3, x4, x5, out);
}